// round 12
// baseline (speedup 1.0000x reference)
#include <cuda_runtime.h>
#include <cuda_bf16.h>
#include <cstdint>

// ---------------------------------------------------------------------------
// AttentionPool: B=8, N=4096, DIM=1536, H=24, hd=64, R=8
// Reformulated (8x FLOP cut), tf32 MMA with integer-domain RNA rounding
// (bits + 0x1000 -> HW truncation == round-to-nearest), double-buffered
// single-sync GEMM stages, conflict-free smem fills.
// ---------------------------------------------------------------------------

#define DIMC   1536
#define NTOK   4096
#define NB     8
#define NH     24
#define HD     64
#define RR     8
#define NG     192
#define SCALE  0.125f
#define MASKW  4088

// ------------------------- scratch (static device memory) ------------------
__device__ float g_x8[64 * DIMC];
__device__ float g_q[64 * DIMC];
__device__ float g_part[6 * 64 * DIMC];
__device__ float g_qk[NB * NG * DIMC];
__device__ float g_p[NB * NG * NTOK];
__device__ float g_y[NB * NG * DIMC];
__device__ float g_xcls[64 * DIMC];
__device__ int   g_maskmode;

// ------------------------- helpers -----------------------------------------
// fp32 bits rounded-to-nearest onto the tf32 grid (HW truncates low 13 bits;
// +0x1000 implements round-half-away; carry into exponent is correct rounding)
__device__ __forceinline__ uint32_t fbits(float f) {
    return __float_as_uint(f) + 0x1000u;
}

__device__ __forceinline__ void mma_tf32(float* c, const uint32_t* a, const uint32_t* b) {
    asm volatile(
        "mma.sync.aligned.m16n8k8.row.col.f32.tf32.tf32.f32 "
        "{%0,%1,%2,%3}, {%4,%5,%6,%7}, {%8,%9}, {%0,%1,%2,%3};"
        : "+f"(c[0]), "+f"(c[1]), "+f"(c[2]), "+f"(c[3])
        : "r"(a[0]), "r"(a[1]), "r"(a[2]), "r"(a[3]),
          "r"(b[0]), "r"(b[1]));
}

// ------------------------- mask dtype detection -----------------------------
__global__ void detect_mask_kernel(const unsigned int* __restrict__ m) {
    __shared__ int s_f, s_nb;
    if (threadIdx.x == 0) { s_f = 0; s_nb = 0; }
    __syncthreads();
    unsigned int w = m[threadIdx.x];
    if (w == 0x3F800000u) atomicOr(&s_f, 1);
    else if (w > 1u)      atomicOr(&s_nb, 1);
    __syncthreads();
    if (threadIdx.x == 0) g_maskmode = s_f ? 2 : (s_nb ? 1 : 0);
}

// ------------------------- gather first 8 tokens ----------------------------
__global__ void gather_x8_kernel(const float* __restrict__ x) {
    int row = blockIdx.x;
    int b = row >> 3, r = row & 7;
    const float* src = x + ((size_t)b * NTOK + r) * DIMC;
    float* dst = g_x8 + (size_t)row * DIMC;
    for (int c = threadIdx.x; c < DIMC; c += blockDim.x) dst[c] = src[c];
}

// ------------------------- small NT GEMM with split-K (fp32) ----------------
__global__ __launch_bounds__(256)
void small_nt_kernel(const float* __restrict__ A, const float* __restrict__ B,
                     float* __restrict__ Cpart) {
    int n0 = blockIdx.x * 64;
    int ks = blockIdx.y;
    int kbase = ks * 256;
    __shared__ float As[64 * 33];
    __shared__ float Bs[64 * 33];
    int tid = threadIdx.x;
    int tx = tid & 15, ty = tid >> 4;
    float acc[4][4];
#pragma unroll
    for (int i = 0; i < 4; i++)
#pragma unroll
        for (int j = 0; j < 4; j++) acc[i][j] = 0.f;

    for (int kt = 0; kt < 8; kt++) {
        int kb = kbase + kt * 32;
        __syncthreads();
#pragma unroll
        for (int j = 0; j < 2; j++) {
            int idx = tid + 256 * j;
            int m = idx >> 3, k4 = (idx & 7) * 4;
            float4 va = *(const float4*)&A[(size_t)m * DIMC + kb + k4];
            As[m * 33 + k4 + 0] = va.x; As[m * 33 + k4 + 1] = va.y;
            As[m * 33 + k4 + 2] = va.z; As[m * 33 + k4 + 3] = va.w;
            float4 vb = *(const float4*)&B[(size_t)(n0 + m) * DIMC + kb + k4];
            Bs[m * 33 + k4 + 0] = vb.x; Bs[m * 33 + k4 + 1] = vb.y;
            Bs[m * 33 + k4 + 2] = vb.z; Bs[m * 33 + k4 + 3] = vb.w;
        }
        __syncthreads();
#pragma unroll
        for (int k = 0; k < 32; k++) {
            float a[4], bb[4];
#pragma unroll
            for (int i = 0; i < 4; i++) a[i]  = As[(ty * 4 + i) * 33 + k];
#pragma unroll
            for (int j = 0; j < 4; j++) bb[j] = Bs[(tx * 4 + j) * 33 + k];
#pragma unroll
            for (int i = 0; i < 4; i++)
#pragma unroll
                for (int j = 0; j < 4; j++) acc[i][j] += a[i] * bb[j];
        }
    }
#pragma unroll
    for (int i = 0; i < 4; i++)
#pragma unroll
        for (int j = 0; j < 4; j++)
            Cpart[(size_t)ks * 64 * DIMC + (ty * 4 + i) * DIMC + n0 + tx * 4 + j] = acc[i][j];
}

__global__ void reduce_q_kernel() {
    int i = blockIdx.x * 256 + threadIdx.x;
    if (i < 64 * DIMC) {
        float s = 0.f;
#pragma unroll
        for (int ks = 0; ks < 6; ks++) s += g_part[(size_t)ks * 64 * DIMC + i];
        g_q[i] = s * SCALE;
    }
}

__global__ void reduce_out_kernel(const float* __restrict__ bp, float* __restrict__ out) {
    int i = blockIdx.x * 256 + threadIdx.x;
    if (i < 64 * DIMC) {
        float s = bp[i % DIMC];
#pragma unroll
        for (int ks = 0; ks < 6; ks++) s += g_part[(size_t)ks * 64 * DIMC + i];
        out[i] = s;
    }
}

// ------------------------- qk = q @ Wk per head -----------------------------
__global__ __launch_bounds__(128)
void qk_kernel(const float* __restrict__ Wk) {
    int b = blockIdx.z, h = blockIdx.y;
    int c = blockIdx.x * 128 + threadIdx.x;
    __shared__ float qs[8][64];
    for (int idx = threadIdx.x; idx < 512; idx += 128) {
        int r = idx >> 6, d = idx & 63;
        qs[r][d] = g_q[(size_t)(b * 8 + r) * DIMC + h * HD + d];
    }
    __syncthreads();
    float acc[8];
#pragma unroll
    for (int r = 0; r < 8; r++) acc[r] = 0.f;
    for (int d = 0; d < 64; d++) {
        float w = Wk[(size_t)(h * HD + d) * DIMC + c];
#pragma unroll
        for (int r = 0; r < 8; r++) acc[r] += qs[r][d] * w;
    }
#pragma unroll
    for (int r = 0; r < 8; r++)
        g_qk[(size_t)(b * NG + h * 8 + r) * DIMC + c] = acc[r];
}

// ------------------------- logits: C[192,4096] = qk * x^T (NT, tf32) --------
// smem: As [k32][m64] stride 68 (stores: bank 4k+m lane-distinct; frag: 4t+g)
//       Bs [k32][n128] stride 132 (stores: bank 4k+n lane-distinct; frag: 4t+g)
__global__ __launch_bounds__(256)
void gemm_logits_kernel(const float* __restrict__ x) {
    int b = blockIdx.z;
    const float* A = g_qk + (size_t)b * NG * DIMC;
    const float* B = x + (size_t)b * NTOK * DIMC;
    float* C = g_p + (size_t)b * NG * NTOK;
    int m0 = blockIdx.y * 64, n0 = blockIdx.x * 128;
    __shared__ uint32_t As[2][32 * 68];
    __shared__ uint32_t Bs[2][32 * 132];
    int tid = threadIdx.x, lane = tid & 31, warp = tid >> 5;
    int wm = warp >> 2, wn = warp & 3;
    int g = lane >> 2, t = lane & 3;
    float acc[2][4][4];
#pragma unroll
    for (int mi = 0; mi < 2; mi++)
#pragma unroll
        for (int ni = 0; ni < 4; ni++)
#pragma unroll
            for (int q = 0; q < 4; q++) acc[mi][ni][q] = 0.f;

    int am = tid & 63;
    int as0 = tid >> 6;                 // A k-float4 slots as0, as0+4
    int bn = tid & 127;
    int bs0 = tid >> 7;                 // B k-float4 slots bs0, +2, +4, +6
    const float* Ap = A + (size_t)(m0 + am) * DIMC;
    const float* Bp = B + (size_t)(n0 + bn) * DIMC;
    const int KT = DIMC / 32;           // 48

    float4 ra[2], rb[4];
#pragma unroll
    for (int j = 0; j < 2; j++) ra[j] = *(const float4*)(Ap + (as0 + 4 * j) * 4);
#pragma unroll
    for (int j = 0; j < 4; j++) rb[j] = *(const float4*)(Bp + (bs0 + 2 * j) * 4);
#pragma unroll
    for (int j = 0; j < 2; j++) {
        int kw = (as0 + 4 * j) * 4;
        As[0][(kw + 0) * 68 + am] = fbits(ra[j].x);
        As[0][(kw + 1) * 68 + am] = fbits(ra[j].y);
        As[0][(kw + 2) * 68 + am] = fbits(ra[j].z);
        As[0][(kw + 3) * 68 + am] = fbits(ra[j].w);
    }
#pragma unroll
    for (int j = 0; j < 4; j++) {
        int kw = (bs0 + 2 * j) * 4;
        Bs[0][(kw + 0) * 132 + bn] = fbits(rb[j].x);
        Bs[0][(kw + 1) * 132 + bn] = fbits(rb[j].y);
        Bs[0][(kw + 2) * 132 + bn] = fbits(rb[j].z);
        Bs[0][(kw + 3) * 132 + bn] = fbits(rb[j].w);
    }

    for (int kt = 0; kt < KT; kt++) {
        __syncthreads();
        int cur = kt & 1;
        bool more = (kt + 1 < KT);
        if (more) {
            int ko = (kt + 1) * 32;
#pragma unroll
            for (int j = 0; j < 2; j++) ra[j] = *(const float4*)(Ap + ko + (as0 + 4 * j) * 4);
#pragma unroll
            for (int j = 0; j < 4; j++) rb[j] = *(const float4*)(Bp + ko + (bs0 + 2 * j) * 4);
        }
#pragma unroll
        for (int kk = 0; kk < 4; kk++) {
            uint32_t af[2][4];
#pragma unroll
            for (int mi = 0; mi < 2; mi++) {
                int m = wm * 32 + mi * 16 + g;
                int kb0 = (kk * 8 + t) * 68, kb1 = (kk * 8 + t + 4) * 68;
                af[mi][0] = As[cur][kb0 + m];
                af[mi][1] = As[cur][kb0 + m + 8];
                af[mi][2] = As[cur][kb1 + m];
                af[mi][3] = As[cur][kb1 + m + 8];
            }
#pragma unroll
            for (int ni = 0; ni < 4; ni++) {
                int n = wn * 32 + ni * 8 + g;
                uint32_t bf[2] = { Bs[cur][(kk * 8 + t) * 132 + n],
                                   Bs[cur][(kk * 8 + t + 4) * 132 + n] };
                mma_tf32(acc[0][ni], af[0], bf);
                mma_tf32(acc[1][ni], af[1], bf);
            }
        }
        if (more) {
            int nxt = cur ^ 1;
#pragma unroll
            for (int j = 0; j < 2; j++) {
                int kw = (as0 + 4 * j) * 4;
                As[nxt][(kw + 0) * 68 + am] = fbits(ra[j].x);
                As[nxt][(kw + 1) * 68 + am] = fbits(ra[j].y);
                As[nxt][(kw + 2) * 68 + am] = fbits(ra[j].z);
                As[nxt][(kw + 3) * 68 + am] = fbits(ra[j].w);
            }
#pragma unroll
            for (int j = 0; j < 4; j++) {
                int kw = (bs0 + 2 * j) * 4;
                Bs[nxt][(kw + 0) * 132 + bn] = fbits(rb[j].x);
                Bs[nxt][(kw + 1) * 132 + bn] = fbits(rb[j].y);
                Bs[nxt][(kw + 2) * 132 + bn] = fbits(rb[j].z);
                Bs[nxt][(kw + 3) * 132 + bn] = fbits(rb[j].w);
            }
        }
    }
#pragma unroll
    for (int mi = 0; mi < 2; mi++)
#pragma unroll
        for (int ni = 0; ni < 4; ni++) {
            int row = m0 + wm * 32 + mi * 16 + g;
            int col = n0 + wn * 32 + ni * 8 + 2 * t;
            float2 v0 = make_float2(acc[mi][ni][0], acc[mi][ni][1]);
            float2 v1 = make_float2(acc[mi][ni][2], acc[mi][ni][3]);
            *(float2*)&C[(size_t)row * NTOK + col] = v0;
            *(float2*)&C[(size_t)(row + 8) * NTOK + col] = v1;
        }
}

// ------------------------- masked softmax over n ----------------------------
__global__ __launch_bounds__(256)
void softmax_kernel(const void* __restrict__ mask) {
    int b = blockIdx.y, gg = blockIdx.x;
    int r = gg & 7;
    float* row = g_p + (size_t)(b * NG + gg) * NTOK;
    int tid = threadIdx.x, lane = tid & 31, warp = tid >> 5;
    int mode = g_maskmode;
    __shared__ float s1[8], s2[8];

    float vals[16];
    float mx = -1e30f;
#pragma unroll
    for (int j = 0; j < 16; j++) {
        int n = j * 256 + tid;
        float v = row[n];
        bool keep;
        if (n < RR) {
            keep = (n == r);
        } else {
            int mi = (b * RR + r) * MASKW + (n - RR);
            if (mode == 0)      keep = ((const int*)mask)[mi] != 0;
            else if (mode == 1) keep = ((const unsigned char*)mask)[mi] != 0;
            else                keep = ((const float*)mask)[mi] != 0.f;
        }
        v = keep ? v : -1e30f;
        vals[j] = v;
        mx = fmaxf(mx, v);
    }
#pragma unroll
    for (int o = 16; o > 0; o >>= 1) mx = fmaxf(mx, __shfl_xor_sync(0xffffffffu, mx, o));
    if (lane == 0) s1[warp] = mx;
    __syncthreads();
    mx = s1[0];
#pragma unroll
    for (int w = 1; w < 8; w++) mx = fmaxf(mx, s1[w]);

    float sum = 0.f;
#pragma unroll
    for (int j = 0; j < 16; j++) {
        float e = expf(vals[j] - mx);
        vals[j] = e;
        sum += e;
    }
#pragma unroll
    for (int o = 16; o > 0; o >>= 1) sum += __shfl_xor_sync(0xffffffffu, sum, o);
    if (lane == 0) s2[warp] = sum;
    __syncthreads();
    sum = 0.f;
#pragma unroll
    for (int w = 0; w < 8; w++) sum += s2[w];
    float inv = 1.f / sum;
#pragma unroll
    for (int j = 0; j < 16; j++) row[j * 256 + tid] = vals[j] * inv;
}

// ------------------------- y: C[192,1536] = p * x (NN, tf32) ----------------
// smem: As [k32][m64] stride 68 (both conflict-free);
//       Bs [k32][c128] stride 136 (frag conflict-free; stores coalesced-first)
__global__ __launch_bounds__(256)
void gemm_y_kernel(const float* __restrict__ x) {
    int b = blockIdx.z;
    const float* A = g_p + (size_t)b * NG * NTOK;
    const float* B = x + (size_t)b * NTOK * DIMC;
    float* C = g_y + (size_t)b * NG * DIMC;
    int m0 = blockIdx.y * 64, c0 = blockIdx.x * 128;
    __shared__ uint32_t As[2][32 * 68];
    __shared__ uint32_t Bs[2][32 * 136];
    int tid = threadIdx.x, lane = tid & 31, warp = tid >> 5;
    int wm = warp >> 2, wn = warp & 3;
    int g = lane >> 2, t = lane & 3;
    float acc[2][4][4];
#pragma unroll
    for (int mi = 0; mi < 2; mi++)
#pragma unroll
        for (int ni = 0; ni < 4; ni++)
#pragma unroll
            for (int q = 0; q < 4; q++) acc[mi][ni][q] = 0.f;

    int am = tid & 63;
    int as0 = tid >> 6;
    int bk = tid >> 3;                  // B row k (0..31), 8 threads per row
    int bc0 = (tid & 7) * 4;
    const float* Ap = A + (size_t)(m0 + am) * NTOK;
    const float* Bp = B + (size_t)bk * DIMC + c0;
    const int KT = NTOK / 32;           // 128

    float4 ra[2], rb[4];
#pragma unroll
    for (int j = 0; j < 2; j++) ra[j] = *(const float4*)(Ap + (as0 + 4 * j) * 4);
#pragma unroll
    for (int j = 0; j < 4; j++) rb[j] = *(const float4*)(Bp + bc0 + 32 * j);
#pragma unroll
    for (int j = 0; j < 2; j++) {
        int kw = (as0 + 4 * j) * 4;
        As[0][(kw + 0) * 68 + am] = fbits(ra[j].x);
        As[0][(kw + 1) * 68 + am] = fbits(ra[j].y);
        As[0][(kw + 2) * 68 + am] = fbits(ra[j].z);
        As[0][(kw + 3) * 68 + am] = fbits(ra[j].w);
    }
#pragma unroll
    for (int j = 0; j < 4; j++) {
        int cw = bc0 + 32 * j;
        Bs[0][bk * 136 + cw + 0] = fbits(rb[j].x);
        Bs[0][bk * 136 + cw + 1] = fbits(rb[j].y);
        Bs[0][bk * 136 + cw + 2] = fbits(rb[j].z);
        Bs[0][bk * 136 + cw + 3] = fbits(rb[j].w);
    }

    for (int kt = 0; kt < KT; kt++) {
        __syncthreads();
        int cur = kt & 1;
        bool more = (kt + 1 < KT);
        if (more) {
            int ko = (kt + 1) * 32;
#pragma unroll
            for (int j = 0; j < 2; j++) ra[j] = *(const float4*)(Ap + ko + (as0 + 4 * j) * 4);
#pragma unroll
            for (int j = 0; j < 4; j++) rb[j] = *(const float4*)(Bp + (size_t)ko * DIMC + bc0 + 32 * j);
        }
#pragma unroll
        for (int kk = 0; kk < 4; kk++) {
            uint32_t af[2][4];
#pragma unroll
            for (int mi = 0; mi < 2; mi++) {
                int m = wm * 32 + mi * 16 + g;
                int kb0 = (kk * 8 + t) * 68, kb1 = (kk * 8 + t + 4) * 68;
                af[mi][0] = As[cur][kb0 + m];
                af[mi][1] = As[cur][kb0 + m + 8];
                af[mi][2] = As[cur][kb1 + m];
                af[mi][3] = As[cur][kb1 + m + 8];
            }
#pragma unroll
            for (int ni = 0; ni < 4; ni++) {
                int c = wn * 32 + ni * 8 + g;
                uint32_t bf[2] = { Bs[cur][(kk * 8 + t) * 136 + c],
                                   Bs[cur][(kk * 8 + t + 4) * 136 + c] };
                mma_tf32(acc[0][ni], af[0], bf);
                mma_tf32(acc[1][ni], af[1], bf);
            }
        }
        if (more) {
            int nxt = cur ^ 1;
#pragma unroll
            for (int j = 0; j < 2; j++) {
                int kw = (as0 + 4 * j) * 4;
                As[nxt][(kw + 0) * 68 + am] = fbits(ra[j].x);
                As[nxt][(kw + 1) * 68 + am] = fbits(ra[j].y);
                As[nxt][(kw + 2) * 68 + am] = fbits(ra[j].z);
                As[nxt][(kw + 3) * 68 + am] = fbits(ra[j].w);
            }
#pragma unroll
            for (int j = 0; j < 4; j++) {
                int cw = bc0 + 32 * j;
                Bs[nxt][bk * 136 + cw + 0] = fbits(rb[j].x);
                Bs[nxt][bk * 136 + cw + 1] = fbits(rb[j].y);
                Bs[nxt][bk * 136 + cw + 2] = fbits(rb[j].z);
                Bs[nxt][bk * 136 + cw + 3] = fbits(rb[j].w);
            }
        }
    }
#pragma unroll
    for (int mi = 0; mi < 2; mi++)
#pragma unroll
        for (int ni = 0; ni < 4; ni++) {
            int row = m0 + wm * 32 + mi * 16 + g;
            int col = c0 + wn * 32 + ni * 8 + 2 * t;
            float2 v0 = make_float2(acc[mi][ni][0], acc[mi][ni][1]);
            float2 v1 = make_float2(acc[mi][ni][2], acc[mi][ni][3]);
            *(float2*)&C[(size_t)row * DIMC + col] = v0;
            *(float2*)&C[(size_t)(row + 8) * DIMC + col] = v1;
        }
}

// ------------------------- xcls: per-head Wv projection of y ----------------
__global__ __launch_bounds__(256)
void xcls_kernel(const float* __restrict__ Wv) {
    int h = blockIdx.x, b = blockIdx.y;
    __shared__ float ys[8][64];
    __shared__ float wvs[64][65];
    int tid = threadIdx.x;
    int r = tid >> 5, lane = tid & 31;
    int d0 = lane * 2;
    float a0 = 0.f, a1 = 0.f;
    for (int c0 = 0; c0 < DIMC; c0 += 64) {
        __syncthreads();
        for (int idx = tid; idx < 512; idx += 256) {
            int rr = idx >> 6, cc = idx & 63;
            ys[rr][cc] = g_y[(size_t)(b * NG + h * 8 + rr) * DIMC + c0 + cc];
        }
        for (int idx = tid; idx < 4096; idx += 256) {
            int dd = idx >> 6, cc = idx & 63;
            wvs[dd][cc] = Wv[(size_t)(h * HD + dd) * DIMC + c0 + cc];
        }
        __syncthreads();
#pragma unroll
        for (int cc = 0; cc < 64; cc++) {
            float yv = ys[r][cc];
            a0 += yv * wvs[d0][cc];
            a1 += yv * wvs[d0 + 1][cc];
        }
    }
    g_xcls[(size_t)(b * 8 + r) * DIMC + h * HD + d0]     = a0;
    g_xcls[(size_t)(b * 8 + r) * DIMC + h * HD + d0 + 1] = a1;
}

// ---------------------------------------------------------------------------
extern "C" void kernel_launch(void* const* d_in, const int* in_sizes, int n_in,
                              void* d_out, int out_size) {
    const float* x    = (const float*)d_in[0];
    const void*  mask = d_in[1];
    const float* Wq   = (const float*)d_in[2];
    const float* Wk   = (const float*)d_in[3];
    const float* Wv   = (const float*)d_in[4];
    const float* Wp   = (const float*)d_in[5];
    const float* bp   = (const float*)d_in[6];
    float* out = (float*)d_out;

    float* d_x8;   cudaGetSymbolAddress((void**)&d_x8,   g_x8);
    float* d_part; cudaGetSymbolAddress((void**)&d_part, g_part);
    float* d_xcls; cudaGetSymbolAddress((void**)&d_xcls, g_xcls);

    detect_mask_kernel<<<1, 128>>>((const unsigned int*)mask);
    gather_x8_kernel<<<64, 256>>>(x);

    small_nt_kernel<<<dim3(24, 6), 256>>>(d_x8, Wq, d_part);
    reduce_q_kernel<<<384, 256>>>();

    qk_kernel<<<dim3(12, NH, NB), 128>>>(Wk);

    gemm_logits_kernel<<<dim3(32, 3, NB), 256>>>(x);
    softmax_kernel<<<dim3(NG, NB), 256>>>(mask);
    gemm_y_kernel<<<dim3(12, 3, NB), 256>>>(x);

    xcls_kernel<<<dim3(NH, NB), 256>>>(Wv);
    small_nt_kernel<<<dim3(24, 6), 256>>>(d_xcls, Wp, d_part);
    reduce_out_kernel<<<384, 256>>>(bp, out);
}

// round 14
// speedup vs baseline: 2.0013x; 2.0013x over previous
#include <cuda_runtime.h>
#include <cstdint>

// ---------------------------------------------------------------------------
// AttentionPool: B=8, N=4096, DIM=1536, H=24, hd=64, R=8
// Reformulated (8x FLOP cut), tf32 MMA (integer-RNA rounding, validated
// rel_err 3.17e-4), BM=192 full-M tiles (x read once per GEMM),
// cp.async double-buffered pipeline, coalesced loads, conflict-free frags.
// ---------------------------------------------------------------------------

#define DIMC   1536
#define NTOK   4096
#define NB     8
#define NH     24
#define HD     64
#define RR     8
#define NG     192
#define SCALE  0.125f
#define MASKW  4088

// ------------------------- scratch (static device memory) ------------------
__device__ float g_x8[64 * DIMC];
__device__ float g_q[64 * DIMC];
__device__ float g_part[6 * 64 * DIMC];
__device__ float g_qk[NB * NG * DIMC];            // pre-rounded tf32 bits
__device__ float g_p[NB * NG * NTOK];             // logits -> probs (rounded)
__device__ float g_ypart[2 * NB * NG * DIMC];     // y split-K partials
__device__ float g_xcls[64 * DIMC];
__device__ int   g_maskmode;

// ------------------------- helpers -----------------------------------------
// round fp32 bits to nearest tf32 (HW truncates low 13 bits; +0x1000 = RNA)
__device__ __forceinline__ float rfloat(float f) {
    return __uint_as_float(__float_as_uint(f) + 0x1000u);
}

__device__ __forceinline__ void mma_tf32(float* c, const uint32_t* a, const uint32_t* b) {
    asm volatile(
        "mma.sync.aligned.m16n8k8.row.col.f32.tf32.tf32.f32 "
        "{%0,%1,%2,%3}, {%4,%5,%6,%7}, {%8,%9}, {%0,%1,%2,%3};"
        : "+f"(c[0]), "+f"(c[1]), "+f"(c[2]), "+f"(c[3])
        : "r"(a[0]), "r"(a[1]), "r"(a[2]), "r"(a[3]),
          "r"(b[0]), "r"(b[1]));
}

#define CP16(dst, src) \
    asm volatile("cp.async.ca.shared.global [%0], [%1], 16;" :: "r"(dst), "l"(src) : "memory")
#define CPCOMMIT() asm volatile("cp.async.commit_group;" ::: "memory")
#define CPWAIT1()  asm volatile("cp.async.wait_group 1;" ::: "memory")
#define CPWAIT0()  asm volatile("cp.async.wait_group 0;" ::: "memory")

// smem words: A buffers 2 x 192*36, B buffers 2 x 2304 (64*36 or 32*72)
#define ASZ   6912
#define BSZ   2304
#define SMEM_BYTES ((2 * ASZ + 2 * BSZ) * 4)      // 73728

// ------------------------- mask dtype detection -----------------------------
__global__ void detect_mask_kernel(const unsigned int* __restrict__ m) {
    __shared__ int s_f, s_nb;
    if (threadIdx.x == 0) { s_f = 0; s_nb = 0; }
    __syncthreads();
    unsigned int w = m[threadIdx.x];
    if (w == 0x3F800000u) atomicOr(&s_f, 1);
    else if (w > 1u)      atomicOr(&s_nb, 1);
    __syncthreads();
    if (threadIdx.x == 0) g_maskmode = s_f ? 2 : (s_nb ? 1 : 0);
}

// ------------------------- gather first 8 tokens ----------------------------
__global__ void gather_x8_kernel(const float* __restrict__ x) {
    int row = blockIdx.x;
    int b = row >> 3, r = row & 7;
    const float* src = x + ((size_t)b * NTOK + r) * DIMC;
    float* dst = g_x8 + (size_t)row * DIMC;
    for (int c = threadIdx.x; c < DIMC; c += blockDim.x) dst[c] = src[c];
}

// ------------------------- small NT GEMM with split-K (fp32) ----------------
__global__ __launch_bounds__(256)
void small_nt_kernel(const float* __restrict__ A, const float* __restrict__ B,
                     float* __restrict__ Cpart) {
    int n0 = blockIdx.x * 64;
    int ks = blockIdx.y;
    int kbase = ks * 256;
    __shared__ float As[64 * 33];
    __shared__ float Bs[64 * 33];
    int tid = threadIdx.x;
    int tx = tid & 15, ty = tid >> 4;
    float acc[4][4] = {};

    for (int kt = 0; kt < 8; kt++) {
        int kb = kbase + kt * 32;
        __syncthreads();
#pragma unroll
        for (int j = 0; j < 2; j++) {
            int idx = tid + 256 * j;
            int m = idx >> 3, k4 = (idx & 7) * 4;
            float4 va = *(const float4*)&A[(size_t)m * DIMC + kb + k4];
            As[m * 33 + k4 + 0] = va.x; As[m * 33 + k4 + 1] = va.y;
            As[m * 33 + k4 + 2] = va.z; As[m * 33 + k4 + 3] = va.w;
            float4 vb = *(const float4*)&B[(size_t)(n0 + m) * DIMC + kb + k4];
            Bs[m * 33 + k4 + 0] = vb.x; Bs[m * 33 + k4 + 1] = vb.y;
            Bs[m * 33 + k4 + 2] = vb.z; Bs[m * 33 + k4 + 3] = vb.w;
        }
        __syncthreads();
#pragma unroll
        for (int k = 0; k < 32; k++) {
            float a[4], bb[4];
#pragma unroll
            for (int i = 0; i < 4; i++) a[i]  = As[(ty * 4 + i) * 33 + k];
#pragma unroll
            for (int j = 0; j < 4; j++) bb[j] = Bs[(tx * 4 + j) * 33 + k];
#pragma unroll
            for (int i = 0; i < 4; i++)
#pragma unroll
                for (int j = 0; j < 4; j++) acc[i][j] += a[i] * bb[j];
        }
    }
#pragma unroll
    for (int i = 0; i < 4; i++)
#pragma unroll
        for (int j = 0; j < 4; j++)
            Cpart[(size_t)ks * 64 * DIMC + (ty * 4 + i) * DIMC + n0 + tx * 4 + j] = acc[i][j];
}

__global__ void reduce_q_kernel() {
    int i = blockIdx.x * 256 + threadIdx.x;
    if (i < 64 * DIMC) {
        float s = 0.f;
#pragma unroll
        for (int ks = 0; ks < 6; ks++) s += g_part[(size_t)ks * 64 * DIMC + i];
        g_q[i] = s * SCALE;
    }
}

__global__ void reduce_out_kernel(const float* __restrict__ bp, float* __restrict__ out) {
    int i = blockIdx.x * 256 + threadIdx.x;
    if (i < 64 * DIMC) {
        float s = bp[i % DIMC];
#pragma unroll
        for (int ks = 0; ks < 6; ks++) s += g_part[(size_t)ks * 64 * DIMC + i];
        out[i] = s;
    }
}

// ------------------------- qk = q @ Wk per head (pre-rounded output) --------
__global__ __launch_bounds__(128)
void qk_kernel(const float* __restrict__ Wk) {
    int b = blockIdx.z, h = blockIdx.y;
    int c = blockIdx.x * 128 + threadIdx.x;
    __shared__ float qs[8][64];
    for (int idx = threadIdx.x; idx < 512; idx += 128) {
        int r = idx >> 6, d = idx & 63;
        qs[r][d] = g_q[(size_t)(b * 8 + r) * DIMC + h * HD + d];
    }
    __syncthreads();
    float acc[8] = {};
    for (int d = 0; d < 64; d++) {
        float w = Wk[(size_t)(h * HD + d) * DIMC + c];
#pragma unroll
        for (int r = 0; r < 8; r++) acc[r] += qs[r][d] * w;
    }
#pragma unroll
    for (int r = 0; r < 8; r++)
        g_qk[(size_t)(b * NG + h * 8 + r) * DIMC + c] = rfloat(acc[r]);
}

// ------------------------- logits: C[192,4096] = qk * x^T (NT, tf32) --------
// BM=192 (full), BN=64, BK=32. A/B smem [row][k] stride 36 (frag bank 4g+t).
__global__ __launch_bounds__(256)
void gemm_logits_kernel(const float* __restrict__ x) {
    extern __shared__ uint32_t sm[];
    const int b = blockIdx.z;
    const int n0 = blockIdx.x * 64;
    const float* A = g_qk + (size_t)b * NG * DIMC;
    const float* B = x + (size_t)b * NTOK * DIMC;
    float* C = g_p + (size_t)b * NG * NTOK;
    uint32_t* As = sm;                       // 2 x ASZ
    uint32_t* Bs = sm + 2 * ASZ;             // 2 x BSZ
    const int tid = threadIdx.x, lane = tid & 31, warp = tid >> 5;
    const int wm = warp & 3, wn = warp >> 2;
    const int g = lane >> 2, t = lane & 3;

    const float* agp[6]; uint32_t aso[6];
#pragma unroll
    for (int j = 0; j < 6; j++) {
        int idx = tid + 256 * j; int m = idx >> 3, k4 = (idx & 7) * 4;
        agp[j] = A + (size_t)m * DIMC + k4; aso[j] = m * 36 + k4;
    }
    const float* bgp[2]; uint32_t bso[2];
#pragma unroll
    for (int j = 0; j < 2; j++) {
        int idx = tid + 256 * j; int n = idx >> 3, k4 = (idx & 7) * 4;
        bgp[j] = B + (size_t)(n0 + n) * DIMC + k4; bso[j] = n * 36 + k4;
    }
    uint32_t sA = (uint32_t)__cvta_generic_to_shared(As);
    uint32_t sB = (uint32_t)__cvta_generic_to_shared(Bs);

    float acc[3][4][4] = {};

#pragma unroll
    for (int j = 0; j < 6; j++) CP16(sA + aso[j] * 4, agp[j]);
#pragma unroll
    for (int j = 0; j < 2; j++) CP16(sB + bso[j] * 4, bgp[j]);
    CPCOMMIT();

    const int KT = DIMC / 32;                // 48
    for (int kt = 0; kt < KT; kt++) {
        int cur = kt & 1;
        if (kt + 1 < KT) {
            int ko = (kt + 1) * 32;
            uint32_t ab = sA + ((cur ^ 1) * ASZ) * 4;
            uint32_t bb = sB + ((cur ^ 1) * BSZ) * 4;
#pragma unroll
            for (int j = 0; j < 6; j++) CP16(ab + aso[j] * 4, agp[j] + ko);
#pragma unroll
            for (int j = 0; j < 2; j++) CP16(bb + bso[j] * 4, bgp[j] + ko);
            CPCOMMIT();
            CPWAIT1();
        } else {
            CPWAIT0();
        }
        __syncthreads();
        const uint32_t* Ab = As + cur * ASZ;
        const uint32_t* Bb = Bs + cur * BSZ;
#pragma unroll
        for (int kk = 0; kk < 4; kk++) {
            uint32_t af[3][4];
#pragma unroll
            for (int mi = 0; mi < 3; mi++) {
                int m = wm * 48 + mi * 16 + g;
                af[mi][0] = Ab[m * 36 + kk * 8 + t];
                af[mi][1] = Ab[(m + 8) * 36 + kk * 8 + t];
                af[mi][2] = Ab[m * 36 + kk * 8 + t + 4];
                af[mi][3] = Ab[(m + 8) * 36 + kk * 8 + t + 4];
            }
#pragma unroll
            for (int ni = 0; ni < 4; ni++) {
                int n = wn * 32 + ni * 8 + g;
                uint32_t bf[2] = { Bb[n * 36 + kk * 8 + t] + 0x1000u,
                                   Bb[n * 36 + kk * 8 + t + 4] + 0x1000u };
#pragma unroll
                for (int mi = 0; mi < 3; mi++) mma_tf32(acc[mi][ni], af[mi], bf);
            }
        }
        __syncthreads();
    }
#pragma unroll
    for (int mi = 0; mi < 3; mi++)
#pragma unroll
        for (int ni = 0; ni < 4; ni++) {
            int row = wm * 48 + mi * 16 + g;
            int col = n0 + wn * 32 + ni * 8 + 2 * t;
            *(float2*)&C[(size_t)row * NTOK + col] =
                make_float2(acc[mi][ni][0], acc[mi][ni][1]);
            *(float2*)&C[(size_t)(row + 8) * NTOK + col] =
                make_float2(acc[mi][ni][2], acc[mi][ni][3]);
        }
}

// ------------------------- masked softmax (pre-rounded probs out) -----------
__global__ __launch_bounds__(256)
void softmax_kernel(const void* __restrict__ mask) {
    int b = blockIdx.y, gg = blockIdx.x;
    int r = gg & 7;
    float* row = g_p + (size_t)(b * NG + gg) * NTOK;
    int tid = threadIdx.x, lane = tid & 31, warp = tid >> 5;
    int mode = g_maskmode;
    __shared__ float s1[8], s2[8];

    float vals[16];
    float mx = -1e30f;
#pragma unroll
    for (int j = 0; j < 16; j++) {
        int n = j * 256 + tid;
        float v = row[n];
        bool keep;
        if (n < RR) {
            keep = (n == r);
        } else {
            int mi = (b * RR + r) * MASKW + (n - RR);
            if (mode == 0)      keep = ((const int*)mask)[mi] != 0;
            else if (mode == 1) keep = ((const unsigned char*)mask)[mi] != 0;
            else                keep = ((const float*)mask)[mi] != 0.f;
        }
        v = keep ? v : -1e30f;
        vals[j] = v;
        mx = fmaxf(mx, v);
    }
#pragma unroll
    for (int o = 16; o > 0; o >>= 1) mx = fmaxf(mx, __shfl_xor_sync(0xffffffffu, mx, o));
    if (lane == 0) s1[warp] = mx;
    __syncthreads();
    mx = s1[0];
#pragma unroll
    for (int w = 1; w < 8; w++) mx = fmaxf(mx, s1[w]);

    float sum = 0.f;
#pragma unroll
    for (int j = 0; j < 16; j++) {
        float e = expf(vals[j] - mx);
        vals[j] = e;
        sum += e;
    }
#pragma unroll
    for (int o = 16; o > 0; o >>= 1) sum += __shfl_xor_sync(0xffffffffu, sum, o);
    if (lane == 0) s2[warp] = sum;
    __syncthreads();
    sum = 0.f;
#pragma unroll
    for (int w = 0; w < 8; w++) sum += s2[w];
    float inv = 1.f / sum;
#pragma unroll
    for (int j = 0; j < 16; j++) row[j * 256 + tid] = rfloat(vals[j] * inv);
}

// ------------------------- y: C[192,1536] = p * x (NN, tf32, split-K 2) -----
// BM=192, BN=64 (c), BK=32. A smem [m][k] stride 36; B smem [k][c] stride 72
// (frag bank 8t+g bijective). Each ks handles 2048 tokens.
__global__ __launch_bounds__(256)
void gemm_y_kernel(const float* __restrict__ x) {
    extern __shared__ uint32_t sm[];
    const int b = blockIdx.z;
    const int c0 = blockIdx.x * 64;
    const int ks = blockIdx.y;
    const int k0 = ks * 2048;
    const float* A = g_p + (size_t)b * NG * NTOK + k0;
    const float* B = x + (size_t)b * NTOK * DIMC + (size_t)k0 * DIMC;
    float* C = g_ypart + ((size_t)ks * NB + b) * NG * DIMC;
    uint32_t* As = sm;
    uint32_t* Bs = sm + 2 * ASZ;
    const int tid = threadIdx.x, lane = tid & 31, warp = tid >> 5;
    const int wm = warp & 3, wn = warp >> 2;
    const int g = lane >> 2, t = lane & 3;

    const float* agp[6]; uint32_t aso[6];
#pragma unroll
    for (int j = 0; j < 6; j++) {
        int idx = tid + 256 * j; int m = idx >> 3, k4 = (idx & 7) * 4;
        agp[j] = A + (size_t)m * NTOK + k4; aso[j] = m * 36 + k4;
    }
    const float* bgp[2]; uint32_t bso[2];
#pragma unroll
    for (int j = 0; j < 2; j++) {
        int idx = tid + 256 * j; int bk = idx >> 4, bc4 = (idx & 15) * 4;
        bgp[j] = B + (size_t)bk * DIMC + c0 + bc4; bso[j] = bk * 72 + bc4;
    }
    uint32_t sA = (uint32_t)__cvta_generic_to_shared(As);
    uint32_t sB = (uint32_t)__cvta_generic_to_shared(Bs);

    float acc[3][4][4] = {};

#pragma unroll
    for (int j = 0; j < 6; j++) CP16(sA + aso[j] * 4, agp[j]);
#pragma unroll
    for (int j = 0; j < 2; j++) CP16(sB + bso[j] * 4, bgp[j]);
    CPCOMMIT();

    const int KT = 2048 / 32;                // 64
    for (int kt = 0; kt < KT; kt++) {
        int cur = kt & 1;
        if (kt + 1 < KT) {
            int ko = (kt + 1) * 32;
            uint32_t ab = sA + ((cur ^ 1) * ASZ) * 4;
            uint32_t bb = sB + ((cur ^ 1) * BSZ) * 4;
#pragma unroll
            for (int j = 0; j < 6; j++) CP16(ab + aso[j] * 4, agp[j] + ko);
#pragma unroll
            for (int j = 0; j < 2; j++) CP16(bb + bso[j] * 4, bgp[j] + (size_t)ko * DIMC);
            CPCOMMIT();
            CPWAIT1();
        } else {
            CPWAIT0();
        }
        __syncthreads();
        const uint32_t* Ab = As + cur * ASZ;
        const uint32_t* Bb = Bs + cur * BSZ;
#pragma unroll
        for (int kk = 0; kk < 4; kk++) {
            uint32_t af[3][4];
#pragma unroll
            for (int mi = 0; mi < 3; mi++) {
                int m = wm * 48 + mi * 16 + g;
                af[mi][0] = Ab[m * 36 + kk * 8 + t];
                af[mi][1] = Ab[(m + 8) * 36 + kk * 8 + t];
                af[mi][2] = Ab[m * 36 + kk * 8 + t + 4];
                af[mi][3] = Ab[(m + 8) * 36 + kk * 8 + t + 4];
            }
#pragma unroll
            for (int ni = 0; ni < 4; ni++) {
                int c = wn * 32 + ni * 8 + g;
                uint32_t bf[2] = { Bb[(kk * 8 + t) * 72 + c] + 0x1000u,
                                   Bb[(kk * 8 + t + 4) * 72 + c] + 0x1000u };
#pragma unroll
                for (int mi = 0; mi < 3; mi++) mma_tf32(acc[mi][ni], af[mi], bf);
            }
        }
        __syncthreads();
    }
#pragma unroll
    for (int mi = 0; mi < 3; mi++)
#pragma unroll
        for (int ni = 0; ni < 4; ni++) {
            int row = wm * 48 + mi * 16 + g;
            int col = c0 + wn * 32 + ni * 8 + 2 * t;
            *(float2*)&C[(size_t)row * DIMC + col] =
                make_float2(acc[mi][ni][0], acc[mi][ni][1]);
            *(float2*)&C[(size_t)(row + 8) * DIMC + col] =
                make_float2(acc[mi][ni][2], acc[mi][ni][3]);
        }
}

// ------------------------- xcls: per-head Wv projection of y (2 parts) -----
__global__ __launch_bounds__(256)
void xcls_kernel(const float* __restrict__ Wv) {
    int h = blockIdx.x, b = blockIdx.y;
    __shared__ float ys[8][64];
    __shared__ float wvs[64][65];
    int tid = threadIdx.x;
    int r = tid >> 5, lane = tid & 31;
    int d0 = lane * 2;
    const size_t PHALF = (size_t)NB * NG * DIMC;
    float a0 = 0.f, a1 = 0.f;
    for (int c0 = 0; c0 < DIMC; c0 += 64) {
        __syncthreads();
        for (int idx = tid; idx < 512; idx += 256) {
            int rr = idx >> 6, cc = idx & 63;
            size_t o = (size_t)(b * NG + h * 8 + rr) * DIMC + c0 + cc;
            ys[rr][cc] = g_ypart[o] + g_ypart[o + PHALF];
        }
        for (int idx = tid; idx < 4096; idx += 256) {
            int dd = idx >> 6, cc = idx & 63;
            wvs[dd][cc] = Wv[(size_t)(h * HD + dd) * DIMC + c0 + cc];
        }
        __syncthreads();
#pragma unroll
        for (int cc = 0; cc < 64; cc++) {
            float yv = ys[r][cc];
            a0 += yv * wvs[d0][cc];
            a1 += yv * wvs[d0 + 1][cc];
        }
    }
    g_xcls[(size_t)(b * 8 + r) * DIMC + h * HD + d0]     = a0;
    g_xcls[(size_t)(b * 8 + r) * DIMC + h * HD + d0 + 1] = a1;
}

// ---------------------------------------------------------------------------
extern "C" void kernel_launch(void* const* d_in, const int* in_sizes, int n_in,
                              void* d_out, int out_size) {
    const float* x    = (const float*)d_in[0];
    const void*  mask = d_in[1];
    const float* Wq   = (const float*)d_in[2];
    const float* Wk   = (const float*)d_in[3];
    const float* Wv   = (const float*)d_in[4];
    const float* Wp   = (const float*)d_in[5];
    const float* bp   = (const float*)d_in[6];
    float* out = (float*)d_out;

    float* d_x8;   cudaGetSymbolAddress((void**)&d_x8,   g_x8);
    float* d_part; cudaGetSymbolAddress((void**)&d_part, g_part);
    float* d_xcls; cudaGetSymbolAddress((void**)&d_xcls, g_xcls);

    cudaFuncSetAttribute(gemm_logits_kernel,
                         cudaFuncAttributeMaxDynamicSharedMemorySize, SMEM_BYTES);
    cudaFuncSetAttribute(gemm_y_kernel,
                         cudaFuncAttributeMaxDynamicSharedMemorySize, SMEM_BYTES);

    detect_mask_kernel<<<1, 128>>>((const unsigned int*)mask);
    gather_x8_kernel<<<64, 256>>>(x);

    small_nt_kernel<<<dim3(24, 6), 256>>>(d_x8, Wq, d_part);
    reduce_q_kernel<<<384, 256>>>();

    qk_kernel<<<dim3(12, NH, NB), 128>>>(Wk);

    gemm_logits_kernel<<<dim3(64, 1, NB), 256, SMEM_BYTES>>>(x);
    softmax_kernel<<<dim3(NG, NB), 256>>>(mask);
    gemm_y_kernel<<<dim3(24, 2, NB), 256, SMEM_BYTES>>>(x);

    xcls_kernel<<<dim3(NH, NB), 256>>>(Wv);
    small_nt_kernel<<<dim3(24, 6), 256>>>(d_xcls, Wp, d_part);
    reduce_out_kernel<<<384, 256>>>(bp, out);
}

// round 16
// speedup vs baseline: 2.0200x; 1.0094x over previous
#include <cuda_runtime.h>
#include <cstdint>

// ---------------------------------------------------------------------------
// AttentionPool: B=8, N=4096, DIM=1536, H=24, hd=64, R=8
// Reformulated (8x FLOP cut), tf32 MMA (integer-RNA rounding), BM=192
// full-M tiles, cp.async double-buffered pipeline. This revision: fused
// launch prefix (gather+reduce_q eliminated) -> gemm_logits is launch idx 3.
// ---------------------------------------------------------------------------

#define DIMC   1536
#define NTOK   4096
#define NB     8
#define NH     24
#define HD     64
#define RR     8
#define NG     192
#define SCALE  0.125f
#define MASKW  4088

// ------------------------- scratch (static device memory) ------------------
__device__ float g_part[6 * 64 * DIMC];
__device__ float g_qk[NB * NG * DIMC];            // pre-rounded tf32
__device__ float g_p[NB * NG * NTOK];             // logits -> probs (rounded)
__device__ float g_ypart[2 * NB * NG * DIMC];     // y split-K partials
__device__ float g_xcls[64 * DIMC];
__device__ int   g_maskmode;

// ------------------------- helpers -----------------------------------------
__device__ __forceinline__ float rfloat(float f) {
    return __uint_as_float(__float_as_uint(f) + 0x1000u);
}

__device__ __forceinline__ void mma_tf32(float* c, const uint32_t* a, const uint32_t* b) {
    asm volatile(
        "mma.sync.aligned.m16n8k8.row.col.f32.tf32.tf32.f32 "
        "{%0,%1,%2,%3}, {%4,%5,%6,%7}, {%8,%9}, {%0,%1,%2,%3};"
        : "+f"(c[0]), "+f"(c[1]), "+f"(c[2]), "+f"(c[3])
        : "r"(a[0]), "r"(a[1]), "r"(a[2]), "r"(a[3]),
          "r"(b[0]), "r"(b[1]));
}

#define CP16(dst, src) \
    asm volatile("cp.async.ca.shared.global [%0], [%1], 16;" :: "r"(dst), "l"(src) : "memory")
#define CPCOMMIT() asm volatile("cp.async.commit_group;" ::: "memory")
#define CPWAIT1()  asm volatile("cp.async.wait_group 1;" ::: "memory")
#define CPWAIT0()  asm volatile("cp.async.wait_group 0;" ::: "memory")

#define ASZ   6912
#define BSZ   2304
#define SMEM_BYTES ((2 * ASZ + 2 * BSZ) * 4)      // 73728

// ------------------------- mask dtype detection -----------------------------
__global__ void detect_mask_kernel(const unsigned int* __restrict__ m) {
    __shared__ int s_f, s_nb;
    if (threadIdx.x == 0) { s_f = 0; s_nb = 0; }
    __syncthreads();
    unsigned int w = m[threadIdx.x];
    if (w == 0x3F800000u) atomicOr(&s_f, 1);
    else if (w > 1u)      atomicOr(&s_nb, 1);
    __syncthreads();
    if (threadIdx.x == 0) g_maskmode = s_f ? 2 : (s_nb ? 1 : 0);
}

// ------------------------- small NT GEMM with split-K (fp32) ----------------
// xmode=1: A row m maps to x[(m>>3)*NTOK + (m&7)] (first 8 tokens per batch)
__global__ __launch_bounds__(256)
void small_nt_kernel(const float* __restrict__ A, const float* __restrict__ B,
                     float* __restrict__ Cpart, int xmode) {
    int n0 = blockIdx.x * 64;
    int ks = blockIdx.y;
    int kbase = ks * 256;
    __shared__ float As[64 * 33];
    __shared__ float Bs[64 * 33];
    int tid = threadIdx.x;
    int tx = tid & 15, ty = tid >> 4;
    float acc[4][4] = {};

    for (int kt = 0; kt < 8; kt++) {
        int kb = kbase + kt * 32;
        __syncthreads();
#pragma unroll
        for (int j = 0; j < 2; j++) {
            int idx = tid + 256 * j;
            int m = idx >> 3, k4 = (idx & 7) * 4;
            size_t arow = xmode ? ((size_t)(m >> 3) * NTOK + (m & 7))
                                : (size_t)m;
            float4 va = *(const float4*)&A[arow * DIMC + kb + k4];
            As[m * 33 + k4 + 0] = va.x; As[m * 33 + k4 + 1] = va.y;
            As[m * 33 + k4 + 2] = va.z; As[m * 33 + k4 + 3] = va.w;
            float4 vb = *(const float4*)&B[(size_t)(n0 + m) * DIMC + kb + k4];
            Bs[m * 33 + k4 + 0] = vb.x; Bs[m * 33 + k4 + 1] = vb.y;
            Bs[m * 33 + k4 + 2] = vb.z; Bs[m * 33 + k4 + 3] = vb.w;
        }
        __syncthreads();
#pragma unroll
        for (int k = 0; k < 32; k++) {
            float a[4], bb[4];
#pragma unroll
            for (int i = 0; i < 4; i++) a[i]  = As[(ty * 4 + i) * 33 + k];
#pragma unroll
            for (int j = 0; j < 4; j++) bb[j] = Bs[(tx * 4 + j) * 33 + k];
#pragma unroll
            for (int i = 0; i < 4; i++)
#pragma unroll
                for (int j = 0; j < 4; j++) acc[i][j] += a[i] * bb[j];
        }
    }
#pragma unroll
    for (int i = 0; i < 4; i++)
#pragma unroll
        for (int j = 0; j < 4; j++)
            Cpart[(size_t)ks * 64 * DIMC + (ty * 4 + i) * DIMC + n0 + tx * 4 + j] = acc[i][j];
}

__global__ void reduce_out_kernel(const float* __restrict__ bp, float* __restrict__ out) {
    int i = blockIdx.x * 256 + threadIdx.x;
    if (i < 64 * DIMC) {
        float s = bp[i % DIMC];
#pragma unroll
        for (int ks = 0; ks < 6; ks++) s += g_part[(size_t)ks * 64 * DIMC + i];
        out[i] = s;
    }
}

// ------------------------- qk = q @ Wk per head (fused q-reduce) ------------
__global__ __launch_bounds__(128)
void qk_kernel(const float* __restrict__ Wk) {
    int b = blockIdx.z, h = blockIdx.y;
    int c = blockIdx.x * 128 + threadIdx.x;
    __shared__ float qs[8][64];
    for (int idx = threadIdx.x; idx < 512; idx += 128) {
        int r = idx >> 6, d = idx & 63;
        size_t o = (size_t)(b * 8 + r) * DIMC + h * HD + d;
        float s = 0.f;
#pragma unroll
        for (int ks = 0; ks < 6; ks++) s += g_part[(size_t)ks * 64 * DIMC + o];
        qs[r][d] = s * SCALE;
    }
    __syncthreads();
    float acc[8] = {};
    for (int d = 0; d < 64; d++) {
        float w = Wk[(size_t)(h * HD + d) * DIMC + c];
#pragma unroll
        for (int r = 0; r < 8; r++) acc[r] += qs[r][d] * w;
    }
#pragma unroll
    for (int r = 0; r < 8; r++)
        g_qk[(size_t)(b * NG + h * 8 + r) * DIMC + c] = rfloat(acc[r]);
}

// ------------------------- logits: C[192,4096] = qk * x^T (NT, tf32) --------
__global__ __launch_bounds__(256)
void gemm_logits_kernel(const float* __restrict__ x) {
    extern __shared__ uint32_t sm[];
    const int b = blockIdx.z;
    const int n0 = blockIdx.x * 64;
    const float* A = g_qk + (size_t)b * NG * DIMC;
    const float* B = x + (size_t)b * NTOK * DIMC;
    float* C = g_p + (size_t)b * NG * NTOK;
    uint32_t* As = sm;
    uint32_t* Bs = sm + 2 * ASZ;
    const int tid = threadIdx.x, lane = tid & 31, warp = tid >> 5;
    const int wm = warp & 3, wn = warp >> 2;
    const int g = lane >> 2, t = lane & 3;

    const float* agp[6]; uint32_t aso[6];
#pragma unroll
    for (int j = 0; j < 6; j++) {
        int idx = tid + 256 * j; int m = idx >> 3, k4 = (idx & 7) * 4;
        agp[j] = A + (size_t)m * DIMC + k4; aso[j] = m * 36 + k4;
    }
    const float* bgp[2]; uint32_t bso[2];
#pragma unroll
    for (int j = 0; j < 2; j++) {
        int idx = tid + 256 * j; int n = idx >> 3, k4 = (idx & 7) * 4;
        bgp[j] = B + (size_t)(n0 + n) * DIMC + k4; bso[j] = n * 36 + k4;
    }
    uint32_t sA = (uint32_t)__cvta_generic_to_shared(As);
    uint32_t sB = (uint32_t)__cvta_generic_to_shared(Bs);

    float acc[3][4][4] = {};

#pragma unroll
    for (int j = 0; j < 6; j++) CP16(sA + aso[j] * 4, agp[j]);
#pragma unroll
    for (int j = 0; j < 2; j++) CP16(sB + bso[j] * 4, bgp[j]);
    CPCOMMIT();

    const int KT = DIMC / 32;                // 48
    for (int kt = 0; kt < KT; kt++) {
        int cur = kt & 1;
        if (kt + 1 < KT) {
            int ko = (kt + 1) * 32;
            uint32_t ab = sA + ((cur ^ 1) * ASZ) * 4;
            uint32_t bb = sB + ((cur ^ 1) * BSZ) * 4;
#pragma unroll
            for (int j = 0; j < 6; j++) CP16(ab + aso[j] * 4, agp[j] + ko);
#pragma unroll
            for (int j = 0; j < 2; j++) CP16(bb + bso[j] * 4, bgp[j] + ko);
            CPCOMMIT();
            CPWAIT1();
        } else {
            CPWAIT0();
        }
        __syncthreads();
        const uint32_t* Ab = As + cur * ASZ;
        const uint32_t* Bb = Bs + cur * BSZ;
#pragma unroll
        for (int kk = 0; kk < 4; kk++) {
            uint32_t af[3][4];
#pragma unroll
            for (int mi = 0; mi < 3; mi++) {
                int m = wm * 48 + mi * 16 + g;
                af[mi][0] = Ab[m * 36 + kk * 8 + t];
                af[mi][1] = Ab[(m + 8) * 36 + kk * 8 + t];
                af[mi][2] = Ab[m * 36 + kk * 8 + t + 4];
                af[mi][3] = Ab[(m + 8) * 36 + kk * 8 + t + 4];
            }
#pragma unroll
            for (int ni = 0; ni < 4; ni++) {
                int n = wn * 32 + ni * 8 + g;
                uint32_t bf[2] = { Bb[n * 36 + kk * 8 + t] + 0x1000u,
                                   Bb[n * 36 + kk * 8 + t + 4] + 0x1000u };
#pragma unroll
                for (int mi = 0; mi < 3; mi++) mma_tf32(acc[mi][ni], af[mi], bf);
            }
        }
        __syncthreads();
    }
#pragma unroll
    for (int mi = 0; mi < 3; mi++)
#pragma unroll
        for (int ni = 0; ni < 4; ni++) {
            int row = wm * 48 + mi * 16 + g;
            int col = n0 + wn * 32 + ni * 8 + 2 * t;
            *(float2*)&C[(size_t)row * NTOK + col] =
                make_float2(acc[mi][ni][0], acc[mi][ni][1]);
            *(float2*)&C[(size_t)(row + 8) * NTOK + col] =
                make_float2(acc[mi][ni][2], acc[mi][ni][3]);
        }
}

// ------------------------- masked softmax (pre-rounded probs out) -----------
__global__ __launch_bounds__(256)
void softmax_kernel(const void* __restrict__ mask) {
    int b = blockIdx.y, gg = blockIdx.x;
    int r = gg & 7;
    float* row = g_p + (size_t)(b * NG + gg) * NTOK;
    int tid = threadIdx.x, lane = tid & 31, warp = tid >> 5;
    int mode = g_maskmode;
    __shared__ float s1[8], s2[8];

    float vals[16];
    float mx = -1e30f;
#pragma unroll
    for (int j = 0; j < 16; j++) {
        int n = j * 256 + tid;
        float v = row[n];
        bool keep;
        if (n < RR) {
            keep = (n == r);
        } else {
            int mi = (b * RR + r) * MASKW + (n - RR);
            if (mode == 0)      keep = ((const int*)mask)[mi] != 0;
            else if (mode == 1) keep = ((const unsigned char*)mask)[mi] != 0;
            else                keep = ((const float*)mask)[mi] != 0.f;
        }
        v = keep ? v : -1e30f;
        vals[j] = v;
        mx = fmaxf(mx, v);
    }
#pragma unroll
    for (int o = 16; o > 0; o >>= 1) mx = fmaxf(mx, __shfl_xor_sync(0xffffffffu, mx, o));
    if (lane == 0) s1[warp] = mx;
    __syncthreads();
    mx = s1[0];
#pragma unroll
    for (int w = 1; w < 8; w++) mx = fmaxf(mx, s1[w]);

    float sum = 0.f;
#pragma unroll
    for (int j = 0; j < 16; j++) {
        float e = expf(vals[j] - mx);
        vals[j] = e;
        sum += e;
    }
#pragma unroll
    for (int o = 16; o > 0; o >>= 1) sum += __shfl_xor_sync(0xffffffffu, sum, o);
    if (lane == 0) s2[warp] = sum;
    __syncthreads();
    sum = 0.f;
#pragma unroll
    for (int w = 0; w < 8; w++) sum += s2[w];
    float inv = 1.f / sum;
#pragma unroll
    for (int j = 0; j < 16; j++) row[j * 256 + tid] = rfloat(vals[j] * inv);
}

// ------------------------- y: C[192,1536] = p * x (NN, tf32, split-K 2) -----
__global__ __launch_bounds__(256)
void gemm_y_kernel(const float* __restrict__ x) {
    extern __shared__ uint32_t sm[];
    const int b = blockIdx.z;
    const int c0 = blockIdx.x * 64;
    const int ks = blockIdx.y;
    const int k0 = ks * 2048;
    const float* A = g_p + (size_t)b * NG * NTOK + k0;
    const float* B = x + (size_t)b * NTOK * DIMC + (size_t)k0 * DIMC;
    float* C = g_ypart + ((size_t)ks * NB + b) * NG * DIMC;
    uint32_t* As = sm;
    uint32_t* Bs = sm + 2 * ASZ;
    const int tid = threadIdx.x, lane = tid & 31, warp = tid >> 5;
    const int wm = warp & 3, wn = warp >> 2;
    const int g = lane >> 2, t = lane & 3;

    const float* agp[6]; uint32_t aso[6];
#pragma unroll
    for (int j = 0; j < 6; j++) {
        int idx = tid + 256 * j; int m = idx >> 3, k4 = (idx & 7) * 4;
        agp[j] = A + (size_t)m * NTOK + k4; aso[j] = m * 36 + k4;
    }
    const float* bgp[2]; uint32_t bso[2];
#pragma unroll
    for (int j = 0; j < 2; j++) {
        int idx = tid + 256 * j; int bk = idx >> 4, bc4 = (idx & 15) * 4;
        bgp[j] = B + (size_t)bk * DIMC + c0 + bc4; bso[j] = bk * 72 + bc4;
    }
    uint32_t sA = (uint32_t)__cvta_generic_to_shared(As);
    uint32_t sB = (uint32_t)__cvta_generic_to_shared(Bs);

    float acc[3][4][4] = {};

#pragma unroll
    for (int j = 0; j < 6; j++) CP16(sA + aso[j] * 4, agp[j]);
#pragma unroll
    for (int j = 0; j < 2; j++) CP16(sB + bso[j] * 4, bgp[j]);
    CPCOMMIT();

    const int KT = 2048 / 32;                // 64
    for (int kt = 0; kt < KT; kt++) {
        int cur = kt & 1;
        if (kt + 1 < KT) {
            int ko = (kt + 1) * 32;
            uint32_t ab = sA + ((cur ^ 1) * ASZ) * 4;
            uint32_t bb = sB + ((cur ^ 1) * BSZ) * 4;
#pragma unroll
            for (int j = 0; j < 6; j++) CP16(ab + aso[j] * 4, agp[j] + ko);
#pragma unroll
            for (int j = 0; j < 2; j++) CP16(bb + bso[j] * 4, bgp[j] + (size_t)ko * DIMC);
            CPCOMMIT();
            CPWAIT1();
        } else {
            CPWAIT0();
        }
        __syncthreads();
        const uint32_t* Ab = As + cur * ASZ;
        const uint32_t* Bb = Bs + cur * BSZ;
#pragma unroll
        for (int kk = 0; kk < 4; kk++) {
            uint32_t af[3][4];
#pragma unroll
            for (int mi = 0; mi < 3; mi++) {
                int m = wm * 48 + mi * 16 + g;
                af[mi][0] = Ab[m * 36 + kk * 8 + t];
                af[mi][1] = Ab[(m + 8) * 36 + kk * 8 + t];
                af[mi][2] = Ab[m * 36 + kk * 8 + t + 4];
                af[mi][3] = Ab[(m + 8) * 36 + kk * 8 + t + 4];
            }
#pragma unroll
            for (int ni = 0; ni < 4; ni++) {
                int c = wn * 32 + ni * 8 + g;
                uint32_t bf[2] = { Bb[(kk * 8 + t) * 72 + c] + 0x1000u,
                                   Bb[(kk * 8 + t + 4) * 72 + c] + 0x1000u };
#pragma unroll
                for (int mi = 0; mi < 3; mi++) mma_tf32(acc[mi][ni], af[mi], bf);
            }
        }
        __syncthreads();
    }
#pragma unroll
    for (int mi = 0; mi < 3; mi++)
#pragma unroll
        for (int ni = 0; ni < 4; ni++) {
            int row = wm * 48 + mi * 16 + g;
            int col = c0 + wn * 32 + ni * 8 + 2 * t;
            *(float2*)&C[(size_t)row * DIMC + col] =
                make_float2(acc[mi][ni][0], acc[mi][ni][1]);
            *(float2*)&C[(size_t)(row + 8) * DIMC + col] =
                make_float2(acc[mi][ni][2], acc[mi][ni][3]);
        }
}

// ------------------------- xcls: per-head Wv projection of y (2 parts) -----
__global__ __launch_bounds__(256)
void xcls_kernel(const float* __restrict__ Wv) {
    int h = blockIdx.x, b = blockIdx.y;
    __shared__ float ys[8][64];
    __shared__ float wvs[64][65];
    int tid = threadIdx.x;
    int r = tid >> 5, lane = tid & 31;
    int d0 = lane * 2;
    const size_t PHALF = (size_t)NB * NG * DIMC;
    float a0 = 0.f, a1 = 0.f;
    for (int c0 = 0; c0 < DIMC; c0 += 64) {
        __syncthreads();
        for (int idx = tid; idx < 512; idx += 256) {
            int rr = idx >> 6, cc = idx & 63;
            size_t o = (size_t)(b * NG + h * 8 + rr) * DIMC + c0 + cc;
            ys[rr][cc] = g_ypart[o] + g_ypart[o + PHALF];
        }
        for (int idx = tid; idx < 4096; idx += 256) {
            int dd = idx >> 6, cc = idx & 63;
            wvs[dd][cc] = Wv[(size_t)(h * HD + dd) * DIMC + c0 + cc];
        }
        __syncthreads();
#pragma unroll
        for (int cc = 0; cc < 64; cc++) {
            float yv = ys[r][cc];
            a0 += yv * wvs[d0][cc];
            a1 += yv * wvs[d0 + 1][cc];
        }
    }
    g_xcls[(size_t)(b * 8 + r) * DIMC + h * HD + d0]     = a0;
    g_xcls[(size_t)(b * 8 + r) * DIMC + h * HD + d0 + 1] = a1;
}

// ---------------------------------------------------------------------------
extern "C" void kernel_launch(void* const* d_in, const int* in_sizes, int n_in,
                              void* d_out, int out_size) {
    const float* x    = (const float*)d_in[0];
    const void*  mask = d_in[1];
    const float* Wq   = (const float*)d_in[2];
    const float* Wk   = (const float*)d_in[3];
    const float* Wv   = (const float*)d_in[4];
    const float* Wp   = (const float*)d_in[5];
    const float* bp   = (const float*)d_in[6];
    float* out = (float*)d_out;

    float* d_part; cudaGetSymbolAddress((void**)&d_part, g_part);
    float* d_xcls; cudaGetSymbolAddress((void**)&d_xcls, g_xcls);

    cudaFuncSetAttribute(gemm_logits_kernel,
                         cudaFuncAttributeMaxDynamicSharedMemorySize, SMEM_BYTES);
    cudaFuncSetAttribute(gemm_y_kernel,
                         cudaFuncAttributeMaxDynamicSharedMemorySize, SMEM_BYTES);

    // launch idx:                                         0
    detect_mask_kernel<<<1, 128>>>((const unsigned int*)mask);
    // q partials straight from x (xmode=1):               1
    small_nt_kernel<<<dim3(24, 6), 256>>>(x, Wq, d_part, 1);
    // qk with fused q-reduction:                          2
    qk_kernel<<<dim3(12, NH, NB), 128>>>(Wk);
    // logits — ncu capture slot:                          3
    gemm_logits_kernel<<<dim3(64, 1, NB), 256, SMEM_BYTES>>>(x);
    softmax_kernel<<<dim3(NG, NB), 256>>>(mask);        // 4
    gemm_y_kernel<<<dim3(24, 2, NB), 256, SMEM_BYTES>>>(x); // 5
    xcls_kernel<<<dim3(NH, NB), 256>>>(Wv);             // 6
    small_nt_kernel<<<dim3(24, 6), 256>>>(d_xcls, Wp, d_part, 0); // 7
    reduce_out_kernel<<<384, 256>>>(bp, out);           // 8
}